// round 5
// baseline (speedup 1.0000x reference)
#include <cuda_runtime.h>
#include <cstdint>

// FieldAwareFM: B=16384, F=10 fields, D=8.
// y[b] = b_lin + sum_f w[xoff[b,f]] + sum_{f<g} <emb[f, xoff[b,g]], emb[g, xoff[b,f]]>
//
// Kernel 1 packs small fields (4..9, 8610 cols) into per-column 9-row blocks
// (+ linear w) so the FFM's "all rows keyed by x_c" land in 3 cache lines.
// Kernel 2: one warp per sample, 90 (pair,half) tasks, pair order g-DESC for
// A-side line sharing. Per-task decode/addressing comes from a shared-memory
// uint4 LUT (no sqrt, no 64-bit index math in the hot loop); V is a byte
// offset (negative-encoded for packed blocks).

#define BATCH      16384
#define NUM_FIELDS 10
#define FACTOR_DIM 8
#define INPUT_DIM  188610
#define NPAIRS     45
#define NPACKCOLS  8610
#define BLK_F      80          // floats per packed block (9*8 + w + pad)
#define BLK_B      (BLK_F*4)   // 320 bytes

__constant__ int c_off[NUM_FIELDS] = {
    0, 100000, 150000, 170000, 180000, 185000, 187000, 188000, 188500, 188600
};
__constant__ int c_pb[6] = { 0, 5000, 7000, 8000, 8500, 8600 };  // fields 4..9

__device__ __align__(128) float g_pack[NPACKCOLS * BLK_F];

// ---------------- pack kernel ----------------
__global__ __launch_bounds__(256) void pack_kernel(
    const float* __restrict__ w,
    const float* __restrict__ emb)
{
    int tid = blockIdx.x * blockDim.x + threadIdx.x;   // [0, 8610*20)
    if (tid >= NPACKCOLS * 20) return;
    int jp = tid / 20;
    int u  = tid % 20;
    int c4 = (jp >= 5000) + (jp >= 7000) + (jp >= 8000) + (jp >= 8500) + (jp >= 8600);
    int c  = 4 + c4;
    int col = c_off[c] + (jp - c_pb[c4]);

    if (u < 18) {
        int s = u >> 1, part = u & 1;
        int f = s + (s >= c);
        const float4 v = *reinterpret_cast<const float4*>(
            emb + ((size_t)f * INPUT_DIM + (size_t)col) * FACTOR_DIM + part * 4);
        *reinterpret_cast<float4*>(g_pack + (size_t)jp * BLK_F + s * 8 + part * 4) = v;
    } else if (u == 18) {
        g_pack[(size_t)jp * BLK_F + 72] = w[col];
    }
}

// ---------------- main kernel ----------------
__global__ __launch_bounds__(128, 14) void ffm_kernel(
    const int*   __restrict__ x,       // (B, 10) int32
    const float* __restrict__ w,       // (INPUT_DIM,)
    const float* __restrict__ blin,    // scalar
    const float* __restrict__ emb,     // (10, INPUT_DIM, 8)
    float*       __restrict__ out)     // (B,)
{
    const unsigned FULL = 0xFFFFFFFFu;

    // Per-task LUT: .x = f*INPUT_DIM*32 (A raw base, bytes)
    //              .y = g*INPUT_DIM*32 (B raw base, bytes)
    //              .z = f*32          (A packed slot offset, bytes)
    //              .w = (g-1)*32      (B packed slot offset, bytes)
    __shared__ uint4 lut[96];
    for (int e = threadIdx.x; e < 96; e += blockDim.x) {
        int f = 0, g = 1;
        int t = e;
        if (t < 2 * NPAIRS) {
            int   p = t >> 1;
            int   r = NPAIRS - p;
            float s = sqrtf((float)(8 * r + 1));
            g = (int)ceilf((s - 1.0f) * 0.5f);
            f = p - NPAIRS + (g * (g + 1)) / 2;
        }
        lut[e] = make_uint4((unsigned)(f * INPUT_DIM * 32),
                            (unsigned)(g * INPUT_DIM * 32),
                            (unsigned)(f * 32),
                            (unsigned)((g - 1) * 32));
    }
    __syncthreads();

    int b    = (blockIdx.x * blockDim.x + threadIdx.x) >> 5;
    int lane = threadIdx.x & 31;
    if (b >= BATCH) return;

    const char* pk = (const char*)g_pack;
    const char* eb = (const char*)emb;

    // Lane f (<10) owns field f. V = byte offset:
    //   packed (f>=4): V = ~pbb (negative), pbb = block byte base
    //   raw    (f<4):  V = xoff * 32
    int   V   = 0;
    float acc = 0.0f;
    if (lane < NUM_FIELDS) {
        int xr = x[b * NUM_FIELDS + lane];
        if (lane >= 4) {
            int pbb = (c_pb[lane - 4] + xr) * BLK_B;
            V   = ~pbb;
            acc = *(const float*)(pk + pbb + 288);        // w folded into block
        } else {
            V   = (xr + c_off[lane]) * 32;
            acc = *(const float*)((const char*)w + (V >> 3));
        }
    }

    const int partB = (lane & 1) << 4;   // 16B half select (t&1 == lane&1)

    float4 va[3], vb[3];
    bool   valid[3];

    #pragma unroll
    for (int k = 0; k < 3; k++) {
        int   t = lane + 32 * k;
        uint4 e = lut[t];
        int   f = (int)(e.z >> 5);
        int   g = (int)(e.w >> 5) + 1;

        int vg = __shfl_sync(FULL, V, g);   // key of A row: emb[f, x_g]
        int vf = __shfl_sync(FULL, V, f);   // key of B row: emb[g, x_f]

        const char* pA = (vg < 0) ? (pk + (~vg) + e.z) : (eb + e.x + (unsigned)vg);
        const char* pB = (vf < 0) ? (pk + (~vf) + e.w) : (eb + e.y + (unsigned)vf);

        valid[k] = t < 2 * NPAIRS;
        if (valid[k]) {
            va[k] = *(const float4*)(pA + partB);
            vb[k] = *(const float4*)(pB + partB);
        }
    }

    #pragma unroll
    for (int k = 0; k < 3; k++) {
        if (valid[k]) {
            acc += va[k].x * vb[k].x + va[k].y * vb[k].y
                 + va[k].z * vb[k].z + va[k].w * vb[k].w;
        }
    }

    #pragma unroll
    for (int o = 16; o > 0; o >>= 1)
        acc += __shfl_xor_sync(FULL, acc, o);

    if (lane == 0)
        out[b] = acc + blin[0];
}

extern "C" void kernel_launch(void* const* d_in, const int* in_sizes, int n_in,
                              void* d_out, int out_size) {
    const int*   x    = (const int*)  d_in[0];
    const float* w    = (const float*)d_in[1];
    const float* blin = (const float*)d_in[2];
    const float* emb  = (const float*)d_in[3];
    float* out = (float*)d_out;

    const int pack_threads = 256;
    const int pack_blocks  = (NPACKCOLS * 20 + pack_threads - 1) / pack_threads;
    pack_kernel<<<pack_blocks, pack_threads>>>(w, emb);

    const int threads = 128;                      // 4 warps = 4 samples / block
    const int blocks  = (BATCH * 32) / threads;   // 4096
    ffm_kernel<<<blocks, threads>>>(x, w, blin, emb, out);
}